// round 10
// baseline (speedup 1.0000x reference)
#include <cuda_runtime.h>
#include <cstdint>

// ---------------------------------------------------------------------------
// OfflineSlidingWindowAttn  (B=2, SQ=SK=2048, HQ=32, HKV=8, D=128, W=512,
// causal, cap=30 tanh, softmax-clip clamp(1.02p-0.01,0,1))
//
// R4-R9 recompute architecture (vs R3's E-in-smem two-pass, 518us @ occ 12.5%):
//   pass 1: QK tf32-mma -> cap -> mask -> exp -> ROW SUMS ONLY (registers)
//   pass 2: recompute QK -> p = clamp(1.02*e/l - 0.01, 0, 1) -> stage p tile
//           through smem (aliases K buffer) -> PV tf32-mma -> store O
// No E buffer => smem 217KB -> 103KB => 2 CTAs/SM (occ 2x), sibling CTA hides
// barrier + LDS + mma latency (issue was 32%). Tensor work x1.5 (QK twice).
// Frozen + audited; resubmitted through broker outages for a clean A/B vs R3.
// ---------------------------------------------------------------------------

#define HEAD_DIM   128
#define NUM_Q_HEAD 32
#define NUM_KV_HEAD 8
#define GQA_GROUPS (NUM_Q_HEAD / NUM_KV_HEAD)
#define WINDOW     512
#define BQ         64
#define BK         64
#define NTHREADS   256

#define QPITCH 132   // floats; 132 % 32 == 4  -> bank = (4*row + col) % 32
#define KPITCH 132
#define VPITCH 136   // 136 % 32 == 8  -> bank = (8*k + n) % 32
#define PPITCH 68    // p tile 64x64, 68 % 32 == 4 -> conflict-free a-frag reads

#define SCALE_QK 0.08838834764831845f          // 1/sqrt(128)
#define CAPV     30.0f
#define SCALE_Y  (SCALE_QK / CAPV)             // y = acc * SCALE_Y (tanh arg)

// smem layout (bytes)
#define SM_Q_OFF   0
#define SM_Q_BYTES (BQ * QPITCH * 4)                 // 33792
#define SM_KP_OFF  (SM_Q_OFF + SM_Q_BYTES)           // K tile, later aliased by P tile
#define SM_KP_BYTES (BK * KPITCH * 4)                // 33792 (>= 64*68*4 = 17408)
#define SM_V_OFF   (SM_KP_OFF + SM_KP_BYTES)
#define SM_V_BYTES (BK * VPITCH * 4)                 // 34816
#define SM_LS_OFF  (SM_V_OFF + SM_V_BYTES)
#define SM_LS_BYTES (BQ * 4)                         // 256
#define SM_LP_OFF  (SM_LS_OFF + SM_LS_BYTES)
#define SM_LP_BYTES (2 * BQ * 4)                     // 512
#define SM_TOTAL   (SM_LP_OFF + SM_LP_BYTES)         // 103680 -> 2 CTAs/SM

__device__ __forceinline__ uint32_t f2tf32(float f) {
    uint32_t u;
    asm("cvt.rna.tf32.f32 %0, %1;" : "=r"(u) : "f"(f));
    return u;
}

__device__ __forceinline__ void mma_tf32(float c[4],
                                         uint32_t a0, uint32_t a1, uint32_t a2, uint32_t a3,
                                         uint32_t b0, uint32_t b1) {
    asm volatile(
        "mma.sync.aligned.m16n8k8.row.col.f32.tf32.tf32.f32 "
        "{%0,%1,%2,%3}, {%4,%5,%6,%7}, {%8,%9}, {%0,%1,%2,%3};"
        : "+f"(c[0]), "+f"(c[1]), "+f"(c[2]), "+f"(c[3])
        : "r"(a0), "r"(a1), "r"(a2), "r"(a3), "r"(b0), "r"(b1));
}

// LDG one 64x128 f32 tile, convert to tf32, STS at the given pitch
__device__ __forceinline__ void load_tile(const float* __restrict__ base,
                                          int kt, size_t row_stride,
                                          uint32_t* __restrict__ dst, int pitch, int tid) {
#pragma unroll
    for (int it = 0; it < (BK * HEAD_DIM / 4) / NTHREADS; ++it) {
        int idx = tid + it * NTHREADS;
        int r = idx >> 5;
        int c = (idx & 31) << 2;
        float4 f = *reinterpret_cast<const float4*>(base + (size_t)(kt + r) * row_stride + c);
        uint4 u;
        u.x = f2tf32(f.x); u.y = f2tf32(f.y);
        u.z = f2tf32(f.z); u.w = f2tf32(f.w);
        *reinterpret_cast<uint4*>(dst + r * pitch + c) = u;
    }
}

// capped logit -> exp(cap*tanh(y)) ; y = acc*SCALE_Y
__device__ __forceinline__ float exp_cap(float y) {
    float capped;
    if (fabsf(y) < 0.25f) {
        // tanh(y) ~ y*(1 + u*(-1/3 + u*(2/15 + u*(-17/315)))), u=y^2
        float u = y * y;
        float p = fmaf(u, -0.05396825397f, 0.13333333333f);
        p = fmaf(u, p, -0.33333333333f);
        p = fmaf(u, p, 1.0f);
        capped = CAPV * y * p;
    } else {
        float x = fminf(fmaxf(2.0f * y, -20.0f), 20.0f);
        float e2x = __expf(x);
        capped = CAPV * (e2x - 1.0f) * __frcp_rn(e2x + 1.0f);
    }
    return __expf(capped);
}

__global__ __launch_bounds__(NTHREADS, 2)
void swa_kernel(const float* __restrict__ q,
                const float* __restrict__ k,
                const float* __restrict__ v,
                float* __restrict__ out,
                int SQ) {
    extern __shared__ char smem[];
    uint32_t* Qs  = reinterpret_cast<uint32_t*>(smem + SM_Q_OFF);
    uint32_t* KPs = reinterpret_cast<uint32_t*>(smem + SM_KP_OFF);  // K tile / P tile
    uint32_t* Vs  = reinterpret_cast<uint32_t*>(smem + SM_V_OFF);
    float*    Ls  = reinterpret_cast<float*>(smem + SM_LS_OFF);
    float*    Lp  = reinterpret_cast<float*>(smem + SM_LP_OFF);

    const int qt = blockIdx.x;
    const int h  = blockIdx.y;
    const int b  = blockIdx.z;
    const int kvh = h / GQA_GROUPS;
    const int qs = qt * BQ;

    const int tid  = threadIdx.x;
    const int warp = tid >> 5;
    const int lane = tid & 31;
    const int g = lane >> 2;   // group id 0..7
    const int m = lane & 3;    // 0..3

    const size_t q_row_stride  = (size_t)NUM_Q_HEAD * HEAD_DIM;   // 4096
    const size_t kv_row_stride = (size_t)NUM_KV_HEAD * HEAD_DIM;  // 1024

    const float* qbase = q + (((size_t)b * SQ + qs) * NUM_Q_HEAD + h) * HEAD_DIM;
    const float* kbase = k + ((size_t)b * SQ * NUM_KV_HEAD + kvh) * HEAD_DIM;
    const float* vbase = v + ((size_t)b * SQ * NUM_KV_HEAD + kvh) * HEAD_DIM;

    // ---- key tile range ----
    int wstart = qs - WINDOW; if (wstart < 0) wstart = 0;
    const int kstart = wstart & ~(BK - 1);
    const int klast  = (qs + BQ - 1) & ~(BK - 1);
    const int ntiles = (klast - kstart) / BK + 1;   // <= 9

    // ---- load Q tile (convert to tf32) ----
#pragma unroll
    for (int it = 0; it < (BQ * HEAD_DIM / 4) / NTHREADS; ++it) {
        int idx = tid + it * NTHREADS;
        int r = idx >> 5;
        int c = (idx & 31) << 2;
        float4 f = *reinterpret_cast<const float4*>(qbase + (size_t)r * q_row_stride + c);
        uint4 u;
        u.x = f2tf32(f.x); u.y = f2tf32(f.y); u.z = f2tf32(f.z); u.w = f2tf32(f.w);
        *reinterpret_cast<uint4*>(Qs + r * QPITCH + c) = u;
    }

    // warp tiling (same for pass1 QK, pass2 QK, and PV rows)
    const int rw = (warp & 3) * 16;   // S row block
    const int cb = (warp >> 2) * 32;  // S col block (4 n-tiles of 8)

    __syncthreads();   // Q tile visible to all warps

    // ---- hoist Q mma fragments to registers for pass 1 ----
    uint32_t qa[16][4];
    {
        const uint32_t* qrow0 = Qs + (rw + g) * QPITCH;
        const uint32_t* qrow1 = Qs + (rw + g + 8) * QPITCH;
#pragma unroll
        for (int ks = 0; ks < 16; ++ks) {
            const int kk = ks * 8;
            qa[ks][0] = qrow0[kk + m];
            qa[ks][1] = qrow1[kk + m];
            qa[ks][2] = qrow0[kk + m + 4];
            qa[ks][3] = qrow1[kk + m + 4];
        }
    }

    // ================= PASS 1: row sums of exp(cap(QK)) =================
    float sum0 = 0.0f, sum1 = 0.0f;   // rows rw+g and rw+g+8

    for (int t = 0; t < ntiles; ++t) {
        const int kt = kstart + t * BK;
        __syncthreads();                    // prior consumers of KPs done
        load_tile(kbase, kt, kv_row_stride, KPs, KPITCH, tid);
        __syncthreads();

        float acc[4][4];
#pragma unroll
        for (int nt = 0; nt < 4; ++nt)
#pragma unroll
            for (int e = 0; e < 4; ++e) acc[nt][e] = 0.0f;

#pragma unroll 4
        for (int ks = 0; ks < 16; ++ks) {
            const int kk = ks * 8;
#pragma unroll
            for (int nt = 0; nt < 4; ++nt) {
                const uint32_t* krow = KPs + (cb + nt * 8 + g) * KPITCH;
                uint32_t b0 = krow[kk + m];
                uint32_t b1 = krow[kk + m + 4];
                mma_tf32(acc[nt], qa[ks][0], qa[ks][1], qa[ks][2], qa[ks][3], b0, b1);
            }
        }

        const bool full = (kt >= qs + BQ - 1 - WINDOW) && (kt + BK - 1 <= qs);
        const int i0 = qs + rw + g;
        const int jb = kt + cb + 2 * m;

#pragma unroll
        for (int nt = 0; nt < 4; ++nt) {
#pragma unroll
            for (int e = 0; e < 4; ++e) {
                float ev = exp_cap(acc[nt][e] * SCALE_Y);
                if (!full) {
                    int i = i0 + ((e >> 1) << 3);
                    int j = jb + nt * 8 + (e & 1);
                    if (j < i - WINDOW || j > i) ev = 0.0f;
                }
                if (e < 2) sum0 += ev; else sum1 += ev;
            }
        }
    }

    // ---- reduce row sums: quad shfl + cross-warp smem combine ----
    sum0 += __shfl_xor_sync(0xffffffff, sum0, 1);
    sum0 += __shfl_xor_sync(0xffffffff, sum0, 2);
    sum1 += __shfl_xor_sync(0xffffffff, sum1, 1);
    sum1 += __shfl_xor_sync(0xffffffff, sum1, 2);
    __syncthreads();            // pass-1 KPs readers done (also orders Lp writes)
    if (m == 0) {
        Lp[(warp >> 2) * BQ + rw + g]     = sum0;
        Lp[(warp >> 2) * BQ + rw + g + 8] = sum1;
    }
    __syncthreads();
    if (tid < BQ) Ls[tid] = 1.02f / (Lp[tid] + Lp[BQ + tid]);
    __syncthreads();

    const float linv0 = Ls[rw + g];
    const float linv1 = Ls[rw + g + 8];

    // ================= PASS 2: recompute QK, clip, PV =================
    const int cb2 = (warp >> 2) * 64;   // output D col block (8 n-tiles of 8)

    float oacc[8][4];
#pragma unroll
    for (int nt = 0; nt < 8; ++nt)
#pragma unroll
        for (int e = 0; e < 4; ++e) oacc[nt][e] = 0.0f;

    for (int t = 0; t < ntiles; ++t) {
        const int kt = kstart + t * BK;
        __syncthreads();                    // prior PV reads of KPs(P)/Vs done
        load_tile(kbase, kt, kv_row_stride, KPs, KPITCH, tid);
        load_tile(vbase, kt, kv_row_stride, Vs, VPITCH, tid);
        __syncthreads();

        // --- recompute S tile (Q frags re-read from smem; qa regs are dead) ---
        float acc[4][4];
#pragma unroll
        for (int nt = 0; nt < 4; ++nt)
#pragma unroll
            for (int e = 0; e < 4; ++e) acc[nt][e] = 0.0f;

        const uint32_t* qrow0 = Qs + (rw + g) * QPITCH;
        const uint32_t* qrow1 = Qs + (rw + g + 8) * QPITCH;
#pragma unroll 4
        for (int ks = 0; ks < 16; ++ks) {
            const int kk = ks * 8;
            uint32_t a0 = qrow0[kk + m];
            uint32_t a1 = qrow1[kk + m];
            uint32_t a2 = qrow0[kk + m + 4];
            uint32_t a3 = qrow1[kk + m + 4];
#pragma unroll
            for (int nt = 0; nt < 4; ++nt) {
                const uint32_t* krow = KPs + (cb + nt * 8 + g) * KPITCH;
                uint32_t b0 = krow[kk + m];
                uint32_t b1 = krow[kk + m + 4];
                mma_tf32(acc[nt], a0, a1, a2, a3, b0, b1);
            }
        }

        // --- epilogue: identical exp/mask as pass 1, then clip to p (tf32) ---
        const bool full = (kt >= qs + BQ - 1 - WINDOW) && (kt + BK - 1 <= qs);
        const int i0 = qs + rw + g;
        const int jb = kt + cb + 2 * m;

        uint32_t pcl[4][4];
#pragma unroll
        for (int nt = 0; nt < 4; ++nt) {
#pragma unroll
            for (int e = 0; e < 4; ++e) {
                float ev = exp_cap(acc[nt][e] * SCALE_Y);
                if (!full) {
                    int i = i0 + ((e >> 1) << 3);
                    int j = jb + nt * 8 + (e & 1);
                    if (j < i - WINDOW || j > i) ev = 0.0f;
                }
                float lin = (e < 2) ? linv0 : linv1;
                float p = fminf(fmaxf(fmaf(ev, lin, -0.01f), 0.0f), 1.0f);
                pcl[nt][e] = f2tf32(p);
            }
        }

        __syncthreads();   // all warps done reading K frags; safe to alias with P

        // --- stage p tile into KPs (pitch 68), STS.64 pairs ---
#pragma unroll
        for (int nt = 0; nt < 4; ++nt) {
            const int col = cb + nt * 8 + 2 * m;
            uint2 p01 = make_uint2(pcl[nt][0], pcl[nt][1]);
            uint2 p23 = make_uint2(pcl[nt][2], pcl[nt][3]);
            *reinterpret_cast<uint2*>(KPs + (rw + g)     * PPITCH + col) = p01;
            *reinterpret_cast<uint2*>(KPs + (rw + g + 8) * PPITCH + col) = p23;
        }
        __syncthreads();

        // --- PV mma: a-frags from P (all 64 S-cols), b-frags from V ---
        const uint32_t* prow0 = KPs + (rw + g) * PPITCH;
        const uint32_t* prow1 = KPs + (rw + g + 8) * PPITCH;
#pragma unroll 2
        for (int ks = 0; ks < 8; ++ks) {
            const int kk = ks * 8;
            uint32_t a0 = prow0[kk + m];
            uint32_t a1 = prow1[kk + m];
            uint32_t a2 = prow0[kk + m + 4];
            uint32_t a3 = prow1[kk + m + 4];
#pragma unroll
            for (int nt = 0; nt < 8; ++nt) {
                const int dcol = cb2 + nt * 8 + g;
                uint32_t b0 = Vs[(kk + m) * VPITCH + dcol];
                uint32_t b1 = Vs[(kk + m + 4) * VPITCH + dcol];
                mma_tf32(oacc[nt], a0, a1, a2, a3, b0, b1);
            }
        }
    }

    // ---- store O ----
    float* obase = out + (((size_t)b * SQ + qs) * NUM_Q_HEAD + h) * HEAD_DIM;
#pragma unroll
    for (int nt = 0; nt < 8; ++nt) {
        const int col = cb2 + nt * 8 + 2 * m;
        float2 v01 = make_float2(oacc[nt][0], oacc[nt][1]);
        float2 v23 = make_float2(oacc[nt][2], oacc[nt][3]);
        *reinterpret_cast<float2*>(obase + (size_t)(rw + g) * q_row_stride + col) = v01;
        *reinterpret_cast<float2*>(obase + (size_t)(rw + g + 8) * q_row_stride + col) = v23;
    }
}

extern "C" void kernel_launch(void* const* d_in, const int* in_sizes, int n_in,
                              void* d_out, int out_size) {
    const float* q = (const float*)d_in[0];
    const float* k = (const float*)d_in[1];
    const float* v = (const float*)d_in[2];
    float* out = (float*)d_out;

    const int SQ = 2048;
    const int B = in_sizes[0] / (SQ * NUM_Q_HEAD * HEAD_DIM);

    cudaFuncSetAttribute(swa_kernel, cudaFuncAttributeMaxDynamicSharedMemorySize, SM_TOTAL);

    dim3 grid(SQ / BQ, NUM_Q_HEAD, B);
    swa_kernel<<<grid, NTHREADS, SM_TOTAL>>>(q, k, v, out, SQ);
}

// round 12
// speedup vs baseline: 1.1196x; 1.1196x over previous
#include <cuda_runtime.h>
#include <cstdint>

// ---------------------------------------------------------------------------
// OfflineSlidingWindowAttn  (B=2, SQ=SK=2048, HQ=32, HKV=8, D=128, W=512,
// causal, cap=30 tanh, softmax-clip clamp(1.02p-0.01,0,1))
//
// R10/R11: R3's E-buffer two-pass (NO recompute) at R4's occupancy.
// Measured: R3 (18 units, 2 w/SMSP) = 518us; R4 (27 units, 4 w/SMSP) = 567us
//  => rate scales ~1.37x with warps/SMSP; recompute tax (1.5x work) loses.
// Fix: 512 threads (16 warps = 4/SMSP) in ONE CTA, E-buffer kept (217KB smem).
//   pass 1: QK tf32-mma -> cap -> mask -> exp -> E tile in smem + row sums
//   pass 2: p = clamp(1.02*e/l - 0.01, 0, 1) -> PV tf32-mma -> store O
// R11: audited, frozen; resubmitted through broker outage.
// ---------------------------------------------------------------------------

#define HEAD_DIM   128
#define NUM_Q_HEAD 32
#define NUM_KV_HEAD 8
#define GQA_GROUPS (NUM_Q_HEAD / NUM_KV_HEAD)
#define WINDOW     512
#define BQ         64
#define BK         64
#define NTHREADS   512

#define QPITCH 132   // floats; 132 % 32 == 4  -> bank = (4*row + col) % 32
#define KPITCH 132
#define VPITCH 136   // 136 % 32 == 8  -> bank = (8*k + n) % 32
#define EPITCH 580   // 580 % 32 == 4

#define SCALE_QK 0.08838834764831845f          // 1/sqrt(128)
#define CAPV     30.0f
#define SCALE_Y  (SCALE_QK / CAPV)             // y = acc * SCALE_Y (tanh arg)

// smem layout (bytes)
#define SM_Q_OFF   0
#define SM_Q_BYTES (BQ * QPITCH * 4)                 // 33792
#define SM_KV_OFF  (SM_Q_OFF + SM_Q_BYTES)
#define SM_KV_BYTES (BK * VPITCH * 4)                // 34816 (K uses pitch 132)
#define SM_E_OFF   (SM_KV_OFF + SM_KV_BYTES)
#define SM_E_BYTES (BQ * EPITCH * 4)                 // 148480
#define SM_L_OFF   (SM_E_OFF + SM_E_BYTES)
#define SM_L_BYTES (BQ * 4)
#define SM_TOTAL   (SM_L_OFF + SM_L_BYTES)           // 217344 -> 1 CTA/SM, 16 warps

__device__ __forceinline__ uint32_t f2tf32(float f) {
    uint32_t u;
    asm("cvt.rna.tf32.f32 %0, %1;" : "=r"(u) : "f"(f));
    return u;
}

__device__ __forceinline__ void mma_tf32(float c[4],
                                         uint32_t a0, uint32_t a1, uint32_t a2, uint32_t a3,
                                         uint32_t b0, uint32_t b1) {
    asm volatile(
        "mma.sync.aligned.m16n8k8.row.col.f32.tf32.tf32.f32 "
        "{%0,%1,%2,%3}, {%4,%5,%6,%7}, {%8,%9}, {%0,%1,%2,%3};"
        : "+f"(c[0]), "+f"(c[1]), "+f"(c[2]), "+f"(c[3])
        : "r"(a0), "r"(a1), "r"(a2), "r"(a3), "r"(b0), "r"(b1));
}

// LDG one 64x128 f32 tile, convert to tf32, STS at the given pitch
__device__ __forceinline__ void load_tile(const float* __restrict__ base,
                                          int kt, size_t row_stride,
                                          uint32_t* __restrict__ dst, int pitch, int tid) {
#pragma unroll
    for (int it = 0; it < (BK * HEAD_DIM / 4) / NTHREADS; ++it) {
        int idx = tid + it * NTHREADS;
        int r = idx >> 5;
        int c = (idx & 31) << 2;
        float4 f = *reinterpret_cast<const float4*>(base + (size_t)(kt + r) * row_stride + c);
        uint4 u;
        u.x = f2tf32(f.x); u.y = f2tf32(f.y);
        u.z = f2tf32(f.z); u.w = f2tf32(f.w);
        *reinterpret_cast<uint4*>(dst + r * pitch + c) = u;
    }
}

// capped logit -> exp(cap*tanh(y)) ; y = acc*SCALE_Y
__device__ __forceinline__ float exp_cap(float y) {
    float capped;
    if (fabsf(y) < 0.25f) {
        // tanh(y) ~ y*(1 + u*(-1/3 + u*(2/15 + u*(-17/315)))), u=y^2
        float u = y * y;
        float p = fmaf(u, -0.05396825397f, 0.13333333333f);
        p = fmaf(u, p, -0.33333333333f);
        p = fmaf(u, p, 1.0f);
        capped = CAPV * y * p;
    } else {
        float x = fminf(fmaxf(2.0f * y, -20.0f), 20.0f);
        float e2x = __expf(x);
        capped = CAPV * (e2x - 1.0f) * __frcp_rn(e2x + 1.0f);
    }
    return __expf(capped);
}

__global__ __launch_bounds__(NTHREADS, 1)
void swa_kernel(const float* __restrict__ q,
                const float* __restrict__ k,
                const float* __restrict__ v,
                float* __restrict__ out,
                int SQ) {
    extern __shared__ char smem[];
    uint32_t* Qs  = reinterpret_cast<uint32_t*>(smem + SM_Q_OFF);
    uint32_t* KVs = reinterpret_cast<uint32_t*>(smem + SM_KV_OFF);
    float*    Es  = reinterpret_cast<float*>(smem + SM_E_OFF);
    float*    Ls  = reinterpret_cast<float*>(smem + SM_L_OFF);

    const int qt = blockIdx.x;
    const int h  = blockIdx.y;
    const int b  = blockIdx.z;
    const int kvh = h / GQA_GROUPS;
    const int qs = qt * BQ;

    const int tid  = threadIdx.x;
    const int warp = tid >> 5;         // 0..15
    const int lane = tid & 31;
    const int g = lane >> 2;   // group id 0..7
    const int m = lane & 3;    // 0..3

    const size_t q_row_stride  = (size_t)NUM_Q_HEAD * HEAD_DIM;   // 4096
    const size_t kv_row_stride = (size_t)NUM_KV_HEAD * HEAD_DIM;  // 1024

    const float* qbase = q + (((size_t)b * SQ + qs) * NUM_Q_HEAD + h) * HEAD_DIM;
    const float* kbase = k + ((size_t)b * SQ * NUM_KV_HEAD + kvh) * HEAD_DIM;
    const float* vbase = v + ((size_t)b * SQ * NUM_KV_HEAD + kvh) * HEAD_DIM;

    // ---- key tile range ----
    int wstart = qs - WINDOW; if (wstart < 0) wstart = 0;
    const int kstart = wstart & ~(BK - 1);
    const int klast  = (qs + BQ - 1) & ~(BK - 1);
    const int ntiles = (klast - kstart) / BK + 1;   // <= 9

    // ---- load Q tile (convert to tf32) ----
#pragma unroll
    for (int it = 0; it < (BQ * HEAD_DIM / 4) / NTHREADS; ++it) {
        int idx = tid + it * NTHREADS;
        int r = idx >> 5;
        int c = (idx & 31) << 2;
        float4 f = *reinterpret_cast<const float4*>(qbase + (size_t)r * q_row_stride + c);
        uint4 u;
        u.x = f2tf32(f.x); u.y = f2tf32(f.y); u.z = f2tf32(f.z); u.w = f2tf32(f.w);
        *reinterpret_cast<uint4*>(Qs + r * QPITCH + c) = u;
    }

    // pass-1 warp tiling: 16 warps cover 64x64 S tile; each warp 16x16 (2 nt)
    const int rw = (warp & 3) * 16;    // S row block
    const int cb = (warp >> 2) * 16;   // S col block (2 n-tiles of 8)

    __syncthreads();   // Q tile visible to all warps

    // ---- hoist Q mma fragments to registers (read smem once, not 9x) ----
    uint32_t qa[16][4];
    {
        const uint32_t* qrow0 = Qs + (rw + g) * QPITCH;
        const uint32_t* qrow1 = Qs + (rw + g + 8) * QPITCH;
#pragma unroll
        for (int ks = 0; ks < 16; ++ks) {
            const int kk = ks * 8;
            qa[ks][0] = qrow0[kk + m];
            qa[ks][1] = qrow1[kk + m];
            qa[ks][2] = qrow0[kk + m + 4];
            qa[ks][3] = qrow1[kk + m + 4];
        }
    }

    // ================= PASS 1: E = exp(cap(QK)) with mask =================
    for (int t = 0; t < ntiles; ++t) {
        const int kt = kstart + t * BK;
        __syncthreads();                    // prev tile's consumers done
        load_tile(kbase, kt, kv_row_stride, KVs, KPITCH, tid);
        __syncthreads();

        float acc[2][4];
#pragma unroll
        for (int nt = 0; nt < 2; ++nt)
#pragma unroll
            for (int e = 0; e < 4; ++e) acc[nt][e] = 0.0f;

#pragma unroll 4
        for (int ks = 0; ks < 16; ++ks) {
            const int kk = ks * 8;
#pragma unroll
            for (int nt = 0; nt < 2; ++nt) {
                const uint32_t* krow = KVs + (cb + nt * 8 + g) * KPITCH;
                uint32_t b0 = krow[kk + m];
                uint32_t b1 = krow[kk + m + 4];
                mma_tf32(acc[nt], qa[ks][0], qa[ks][1], qa[ks][2], qa[ks][3], b0, b1);
            }
        }

        // tile fully inside the window for every (r, c)?
        const bool full = (kt >= qs + BQ - 1 - WINDOW) && (kt + BK - 1 <= qs);
        const int i0 = qs + rw + g;
        const int jb = kt + cb + 2 * m;

        // epilogue: cap, mask, exp, store to E
#pragma unroll
        for (int nt = 0; nt < 2; ++nt) {
#pragma unroll
            for (int e = 0; e < 4; ++e) {
                int r = rw + g + ((e >> 1) << 3);
                int c = cb + nt * 8 + 2 * m + (e & 1);
                float ev = exp_cap(acc[nt][e] * SCALE_Y);
                if (!full) {
                    int i = i0 + ((e >> 1) << 3);
                    int j = jb + nt * 8 + (e & 1);
                    if (j < i - WINDOW || j > i) ev = 0.0f;
                }
                Es[r * EPITCH + t * BK + c] = ev;
            }
        }
    }
    __syncthreads();

    // ---- row sums -> Ls[r] = 1.02 / l  (8 threads per row) ----
    {
        const int r = tid >> 3;       // 0..63
        const int part = tid & 7;
        const int ncols = ntiles * BK;
        float s = 0.0f;
        const float* erow = Es + r * EPITCH;
        for (int c = part; c < ncols; c += 8) s += erow[c];
        s += __shfl_xor_sync(0xffffffff, s, 1);
        s += __shfl_xor_sync(0xffffffff, s, 2);
        s += __shfl_xor_sync(0xffffffff, s, 4);
        if (part == 0) Ls[r] = 1.02f / s;
    }
    __syncthreads();

    // ================= PASS 2: O = clip(p) @ V =================
    // 16 warps cover 64x128 O tile; each warp 16x32 (4 n-tiles of 8)
    const int rw2 = (warp & 3) * 16;
    const int cb2 = (warp >> 2) * 32;

    const float linv0 = Ls[rw2 + g];
    const float linv1 = Ls[rw2 + g + 8];

    float oacc[4][4];
#pragma unroll
    for (int nt = 0; nt < 4; ++nt)
#pragma unroll
        for (int e = 0; e < 4; ++e) oacc[nt][e] = 0.0f;

    for (int t = 0; t < ntiles; ++t) {
        const int kt = kstart + t * BK;
        __syncthreads();                    // prev tile's consumers done
        load_tile(vbase, kt, kv_row_stride, KVs, VPITCH, tid);
        __syncthreads();

        const float* e0row = Es + (rw2 + g) * EPITCH + t * BK;
        const float* e1row = Es + (rw2 + g + 8) * EPITCH + t * BK;
#pragma unroll 2
        for (int ks = 0; ks < 8; ++ks) {
            const int kk = ks * 8;
            float p0 = fmaf(e0row[kk + m],     linv0, -0.01f);
            float p1 = fmaf(e1row[kk + m],     linv1, -0.01f);
            float p2 = fmaf(e0row[kk + m + 4], linv0, -0.01f);
            float p3 = fmaf(e1row[kk + m + 4], linv1, -0.01f);
            p0 = fminf(fmaxf(p0, 0.0f), 1.0f);
            p1 = fminf(fmaxf(p1, 0.0f), 1.0f);
            p2 = fminf(fmaxf(p2, 0.0f), 1.0f);
            p3 = fminf(fmaxf(p3, 0.0f), 1.0f);
            uint32_t a0 = f2tf32(p0);
            uint32_t a1 = f2tf32(p1);
            uint32_t a2 = f2tf32(p2);
            uint32_t a3 = f2tf32(p3);
#pragma unroll
            for (int nt = 0; nt < 4; ++nt) {
                const int dcol = cb2 + nt * 8 + g;
                uint32_t b0 = KVs[(kk + m) * VPITCH + dcol];
                uint32_t b1 = KVs[(kk + m + 4) * VPITCH + dcol];
                mma_tf32(oacc[nt], a0, a1, a2, a3, b0, b1);
            }
        }
    }

    // ---- store O ----
    float* obase = out + (((size_t)b * SQ + qs) * NUM_Q_HEAD + h) * HEAD_DIM;
#pragma unroll
    for (int nt = 0; nt < 4; ++nt) {
        const int col = cb2 + nt * 8 + 2 * m;
        float2 v01 = make_float2(oacc[nt][0], oacc[nt][1]);
        float2 v23 = make_float2(oacc[nt][2], oacc[nt][3]);
        *reinterpret_cast<float2*>(obase + (size_t)(rw2 + g) * q_row_stride + col) = v01;
        *reinterpret_cast<float2*>(obase + (size_t)(rw2 + g + 8) * q_row_stride + col) = v23;
    }
}

extern "C" void kernel_launch(void* const* d_in, const int* in_sizes, int n_in,
                              void* d_out, int out_size) {
    const float* q = (const float*)d_in[0];
    const float* k = (const float*)d_in[1];
    const float* v = (const float*)d_in[2];
    float* out = (float*)d_out;

    const int SQ = 2048;
    const int B = in_sizes[0] / (SQ * NUM_Q_HEAD * HEAD_DIM);

    cudaFuncSetAttribute(swa_kernel, cudaFuncAttributeMaxDynamicSharedMemorySize, SM_TOTAL);

    dim3 grid(SQ / BQ, NUM_Q_HEAD, B);
    swa_kernel<<<grid, NTHREADS, SM_TOTAL>>>(q, k, v, out, SQ);
}